// round 6
// baseline (speedup 1.0000x reference)
#include <cuda_runtime.h>
#include <cstdint>

#define NN 100000   // nodes
#define NE 1600000  // edges
#define NF 128      // input features
#define NH 64       // hidden
#define NC 10       // classes
#define NL 3        // layers
#define NG 1000     // graphs

// Scratch (device globals: no allocation allowed in kernel_launch)
__device__ float g_h[NN * NH];
__device__ float g_agg[NN * NH];
__device__ float g_t[NN * NH];
__device__ float g_pool[NG * NH];
__device__ float g_g2[NG * NH];

// ---------------------------------------------------------------------------
// zero: float4 grid-stride (only used for the small pool buffer now)
// ---------------------------------------------------------------------------
__global__ void zero_kernel(float* __restrict__ p, int n4) {
    float4 z = make_float4(0.f, 0.f, 0.f, 0.f);
    for (int i = blockIdx.x * blockDim.x + threadIdx.x; i < n4;
         i += gridDim.x * blockDim.x)
        reinterpret_cast<float4*>(p)[i] = z;
}

// ---------------------------------------------------------------------------
// GEMM: out[N,64] = act( (A [+ A2]) [N,K] @ W [K,64] + b )
// 64 rows/CTA, 256 threads, 2 rows x 8 cols per thread, K tiled by 64.
// Static smem 33.4KB + low regs -> 6 CTAs/SM (75% occ).
// ZERO_AUX: epilogue zeroes aux rows [row0, row0+64) (fused agg-clear).
// ---------------------------------------------------------------------------
template <int K, bool RELU, bool ADD2, bool ZERO_AUX>
__global__ __launch_bounds__(256, 6)
void gemm_kernel(const float* __restrict__ A,
                 const float* __restrict__ A2,
                 const float* __restrict__ W,
                 const float* __restrict__ bias,
                 float* __restrict__ out,
                 float* __restrict__ aux, int N) {
    constexpr int ROWS = 64;
    constexpr int KC   = 64;        // k-chunk
    constexpr int NCHK = K / KC;
    constexpr int STR  = 68;        // A row stride (pad: banks + float4 align)

    __shared__ float Ws[KC * 64];    // 16 KB
    __shared__ float As[ROWS * STR]; // 17.4 KB

    const int tid  = threadIdx.x;
    const int row0 = blockIdx.x * ROWS;

    const int cb = (tid & 7) * 8;    // column base (8 cols)
    const int r0 = (tid >> 3) * 2;   // row base    (2 rows)

    float acc[2][8];
    #pragma unroll
    for (int j = 0; j < 2; j++)
        #pragma unroll
        for (int c = 0; c < 8; c++) acc[j][c] = 0.f;

    #pragma unroll
    for (int kc = 0; kc < NCHK; kc++) {
        // Stage W chunk (contiguous 4096 floats), float4 coalesced
        {
            const float4* W4 = reinterpret_cast<const float4*>(W) + kc * 1024;
            float4* Ws4 = reinterpret_cast<float4*>(Ws);
            #pragma unroll
            for (int i = 0; i < 4; i++) Ws4[tid + i * 256] = W4[tid + i * 256];
        }
        // Stage A chunk: 64 rows x 64 k, float4, fold A2
        #pragma unroll
        for (int i = 0; i < 4; i++) {
            int idx = tid + i * 256;         // 0..1023
            int r  = idx >> 4;
            int c4 = (idx & 15) * 4;
            int gr = row0 + r;
            float4 v = make_float4(0.f, 0.f, 0.f, 0.f);
            if (gr < N) {
                size_t gi = (size_t)gr * K + kc * KC + c4;
                v = *reinterpret_cast<const float4*>(A + gi);
                if (ADD2) {
                    float4 w = *reinterpret_cast<const float4*>(A2 + gi);
                    v.x += w.x; v.y += w.y; v.z += w.z; v.w += w.w;
                }
            }
            *reinterpret_cast<float4*>(As + r * STR + c4) = v;
        }
        __syncthreads();

        #pragma unroll 8
        for (int k = 0; k < KC; k++) {
            float4 w0 = *reinterpret_cast<const float4*>(Ws + k * 64 + cb);
            float4 w1 = *reinterpret_cast<const float4*>(Ws + k * 64 + cb + 4);
            float a0 = As[r0 * STR + k];
            float a1 = As[(r0 + 1) * STR + k];
            acc[0][0] = fmaf(a0, w0.x, acc[0][0]);
            acc[0][1] = fmaf(a0, w0.y, acc[0][1]);
            acc[0][2] = fmaf(a0, w0.z, acc[0][2]);
            acc[0][3] = fmaf(a0, w0.w, acc[0][3]);
            acc[0][4] = fmaf(a0, w1.x, acc[0][4]);
            acc[0][5] = fmaf(a0, w1.y, acc[0][5]);
            acc[0][6] = fmaf(a0, w1.z, acc[0][6]);
            acc[0][7] = fmaf(a0, w1.w, acc[0][7]);
            acc[1][0] = fmaf(a1, w0.x, acc[1][0]);
            acc[1][1] = fmaf(a1, w0.y, acc[1][1]);
            acc[1][2] = fmaf(a1, w0.z, acc[1][2]);
            acc[1][3] = fmaf(a1, w0.w, acc[1][3]);
            acc[1][4] = fmaf(a1, w1.x, acc[1][4]);
            acc[1][5] = fmaf(a1, w1.y, acc[1][5]);
            acc[1][6] = fmaf(a1, w1.z, acc[1][6]);
            acc[1][7] = fmaf(a1, w1.w, acc[1][7]);
        }
        if (kc + 1 < NCHK) __syncthreads();
    }

    const float4 b0 = *reinterpret_cast<const float4*>(bias + cb);
    const float4 b1 = *reinterpret_cast<const float4*>(bias + cb + 4);

    #pragma unroll
    for (int j = 0; j < 2; j++) {
        int gr = row0 + r0 + j;
        if (gr >= N) break;
        float4 v0, v1;
        v0.x = acc[j][0] + b0.x; v0.y = acc[j][1] + b0.y;
        v0.z = acc[j][2] + b0.z; v0.w = acc[j][3] + b0.w;
        v1.x = acc[j][4] + b1.x; v1.y = acc[j][5] + b1.y;
        v1.z = acc[j][6] + b1.z; v1.w = acc[j][7] + b1.w;
        if (RELU) {
            v0.x = fmaxf(v0.x, 0.f); v0.y = fmaxf(v0.y, 0.f);
            v0.z = fmaxf(v0.z, 0.f); v0.w = fmaxf(v0.w, 0.f);
            v1.x = fmaxf(v1.x, 0.f); v1.y = fmaxf(v1.y, 0.f);
            v1.z = fmaxf(v1.z, 0.f); v1.w = fmaxf(v1.w, 0.f);
        }
        float4* op = reinterpret_cast<float4*>(out + (size_t)gr * 64 + cb);
        op[0] = v0;
        op[1] = v1;
    }

    if (ZERO_AUX) {
        // Zero aux rows [row0, row0+64): 1024 float4s total
        float4 z = make_float4(0.f, 0.f, 0.f, 0.f);
        float4* a4 = reinterpret_cast<float4*>(aux) + (size_t)row0 * 16;
        int lim = (N - row0 < ROWS ? N - row0 : ROWS) * 16;
        for (int i = tid; i < lim; i += 256) a4[i] = z;
    }
}

// ---------------------------------------------------------------------------
// Vector reduction: red.global.add.v4.f32 (sm_90+)
// ---------------------------------------------------------------------------
__device__ __forceinline__ void red_add_v4(float* p, float4 v) {
    asm volatile("red.global.add.v4.f32 [%0], {%1, %2, %3, %4};"
                 :: "l"(p), "f"(v.x), "f"(v.y), "f"(v.z), "f"(v.w)
                 : "memory");
}

// ---------------------------------------------------------------------------
// Edge scatter: agg[dst] += h[src].  Half-warp per edge, float4 per lane.
// ---------------------------------------------------------------------------
__global__ void scatter_kernel(const float* __restrict__ h,
                               const int* __restrict__ ei,
                               float* __restrict__ agg) {
    int warp = blockIdx.x * 8 + (threadIdx.x >> 5);
    int lane = threadIdx.x & 31;
    int e = warp * 2 + (lane >> 4);
    if (e >= NE) return;
    int l16 = lane & 15;
    int s = __ldg(ei + e);
    int d = __ldg(ei + NE + e);
    if ((unsigned)s >= NN || (unsigned)d >= NN) return;
    float4 v = reinterpret_cast<const float4*>(h + (size_t)s * NH)[l16];
    red_add_v4(agg + (size_t)d * NH + l16 * 4, v);
}

// ---------------------------------------------------------------------------
// Global add pool: pool[batch[n]] += h[n].  Half-warp per node.
// ---------------------------------------------------------------------------
__global__ void pool_kernel(const float* __restrict__ h,
                            const int* __restrict__ batch,
                            float* __restrict__ pool) {
    int warp = blockIdx.x * 8 + (threadIdx.x >> 5);
    int lane = threadIdx.x & 31;
    int n = warp * 2 + (lane >> 4);
    if (n >= NN) return;
    int l16 = lane & 15;
    int g = __ldg(batch + n);
    if ((unsigned)g >= NG) return;
    float4 v = reinterpret_cast<const float4*>(h + (size_t)n * NH)[l16];
    red_add_v4(pool + (size_t)g * NH + l16 * 4, v);
}

// ---------------------------------------------------------------------------
// Readout: logits = g2 @ roW + rob; out = log_softmax(logits).
// ---------------------------------------------------------------------------
__global__ void readout_kernel(const float* __restrict__ g2,
                               const float* __restrict__ roW,
                               const float* __restrict__ rob,
                               float* __restrict__ out) {
    int row = blockIdx.x * 8 + (threadIdx.x >> 5);
    if (row >= NG) return;
    int lane = threadIdx.x & 31;

    float acc = 0.f;
    if (lane < NC) {
        acc = rob[lane];
        #pragma unroll
        for (int k = 0; k < NH; k++)
            acc = fmaf(g2[(size_t)row * NH + k], roW[k * NC + lane], acc);
    }
    float m = (lane < NC) ? acc : -3.4e38f;
    #pragma unroll
    for (int o = 16; o > 0; o >>= 1)
        m = fmaxf(m, __shfl_xor_sync(0xffffffffu, m, o));
    float e = (lane < NC) ? expf(acc - m) : 0.f;
    float s = e;
    #pragma unroll
    for (int o = 16; o > 0; o >>= 1)
        s += __shfl_xor_sync(0xffffffffu, s, o);
    if (lane < NC) out[(size_t)row * NC + lane] = acc - m - logf(s);
}

// ---------------------------------------------------------------------------
extern "C" void kernel_launch(void* const* d_in, const int* in_sizes, int n_in,
                              void* d_out, int out_size) {
    const float* x      = (const float*)d_in[0];
    const int*   ei     = (const int*)d_in[1];
    const int*   batch  = (const int*)d_in[2];
    const float* pre_w  = (const float*)d_in[3];
    const float* pre_b  = (const float*)d_in[4];
    const float* w1     = (const float*)d_in[5];
    const float* b1     = (const float*)d_in[6];
    const float* w2     = (const float*)d_in[7];
    const float* b2     = (const float*)d_in[8];
    const float* post_w = (const float*)d_in[9];
    const float* post_b = (const float*)d_in[10];
    const float* ro_w   = (const float*)d_in[11];
    const float* ro_b   = (const float*)d_in[12];
    float*       out    = (float*)d_out;

    float *hP, *aggP, *tP, *poolP, *g2P;
    cudaGetSymbolAddress((void**)&hP,    g_h);
    cudaGetSymbolAddress((void**)&aggP,  g_agg);
    cudaGetSymbolAddress((void**)&tP,    g_t);
    cudaGetSymbolAddress((void**)&poolP, g_pool);
    cudaGetSymbolAddress((void**)&g2P,   g_g2);

    const int GB = (NN + 63) / 64;

    // h = x @ pre_w + pre_b  ; also zero agg for layer 0
    gemm_kernel<NF, false, false, true><<<GB, 256>>>(
        x, nullptr, pre_w, pre_b, hP, aggP, NN);

    for (int l = 0; l < NL; l++) {
        scatter_kernel<<<(NE / 2 + 7) / 8, 256>>>(hP, ei, aggP);
        // t = relu((h + agg) @ w1 + b1)
        gemm_kernel<NH, true, true, false><<<GB, 256>>>(
            hP, aggP, w1 + l * NH * NH, b1 + l * NH, tP, nullptr, NN);
        // h = relu(t @ w2 + b2) ; also zero agg for next layer
        gemm_kernel<NH, true, false, true><<<GB, 256>>>(
            tP, nullptr, w2 + l * NH * NH, b2 + l * NH, hP, aggP, NN);
    }

    zero_kernel<<<64, 256>>>(poolP, NG * NH / 4);
    pool_kernel<<<(NN / 2 + 7) / 8, 256>>>(hP, batch, poolP);
    // g2 = relu(pool @ post_w + post_b)
    gemm_kernel<NH, true, false, false><<<(NG + 63) / 64, 256>>>(
        poolP, nullptr, post_w, post_b, g2P, nullptr, NG);
    readout_kernel<<<(NG + 7) / 8, 256>>>(g2P, ro_w, ro_b, out);
}

// round 7
// speedup vs baseline: 1.4752x; 1.4752x over previous
#include <cuda_runtime.h>
#include <cstdint>

#define NN 100000   // nodes
#define NE 1600000  // edges
#define NF 128      // input features
#define NH 64      // hidden
#define NC 10       // classes
#define NL 3        // layers
#define NG 1000     // graphs

// Scratch (device globals: no allocation allowed in kernel_launch)
__device__ float g_h[NN * NH];
__device__ float g_agg[NN * NH];
__device__ float g_t[NN * NH];
__device__ float g_pool[NG * NH];
__device__ float g_g2[NG * NH];

// ---------------------------------------------------------------------------
// zero: float4 grid-stride (only used for the small pool buffer)
// ---------------------------------------------------------------------------
__global__ void zero_kernel(float* __restrict__ p, int n4) {
    float4 z = make_float4(0.f, 0.f, 0.f, 0.f);
    for (int i = blockIdx.x * blockDim.x + threadIdx.x; i < n4;
         i += gridDim.x * blockDim.x)
        reinterpret_cast<float4*>(p)[i] = z;
}

// ---------------------------------------------------------------------------
// GEMM: out[N,64] = act( (A [+ A2]) [N,K] @ W [K,64] + b )
// 64 rows/CTA, 256 threads. Per-thread tile 4 rows x 4 cols.
// Per k per warp: 4 scalar A-LDS (2 unique addrs, broadcast) + 1 LDS.128 W
// (256B unique) = ~6 crossbar cyc vs 8 FMA cyc -> FMA-bound.
// ZERO_AUX: epilogue zeroes aux rows [row0, row0+64) (fused agg-clear).
// ---------------------------------------------------------------------------
template <int K, bool RELU, bool ADD2, bool ZERO_AUX>
__global__ __launch_bounds__(256, 6)
void gemm_kernel(const float* __restrict__ A,
                 const float* __restrict__ A2,
                 const float* __restrict__ W,
                 const float* __restrict__ bias,
                 float* __restrict__ out,
                 float* __restrict__ aux, int N) {
    constexpr int ROWS = 64;
    constexpr int KC   = 64;        // k-chunk
    constexpr int NCHK = K / KC;
    constexpr int STR  = 68;        // A row stride (pad)

    __shared__ float Ws[KC * 64];    // 16 KB
    __shared__ float As[ROWS * STR]; // 17.4 KB

    const int tid  = threadIdx.x;
    const int row0 = blockIdx.x * ROWS;

    const int cb = (tid & 15) * 4;   // column base (4 cols)
    const int r0 = (tid >> 4) * 4;   // row base    (4 rows)

    float acc[4][4];
    #pragma unroll
    for (int j = 0; j < 4; j++)
        #pragma unroll
        for (int c = 0; c < 4; c++) acc[j][c] = 0.f;

    #pragma unroll
    for (int kc = 0; kc < NCHK; kc++) {
        if (kc > 0) __syncthreads();
        // Stage W chunk (contiguous 4096 floats), float4 coalesced
        {
            const float4* W4 = reinterpret_cast<const float4*>(W) + kc * 1024;
            float4* Ws4 = reinterpret_cast<float4*>(Ws);
            #pragma unroll
            for (int i = 0; i < 4; i++) Ws4[tid + i * 256] = W4[tid + i * 256];
        }
        // Stage A chunk: 64 rows x 64 k, float4, fold A2
        #pragma unroll
        for (int i = 0; i < 4; i++) {
            int idx = tid + i * 256;         // 0..1023
            int r  = idx >> 4;
            int c4 = (idx & 15) * 4;
            int gr = row0 + r;
            float4 v = make_float4(0.f, 0.f, 0.f, 0.f);
            if (gr < N) {
                size_t gi = (size_t)gr * K + kc * KC + c4;
                v = *reinterpret_cast<const float4*>(A + gi);
                if (ADD2) {
                    float4 w = *reinterpret_cast<const float4*>(A2 + gi);
                    v.x += w.x; v.y += w.y; v.z += w.z; v.w += w.w;
                }
            }
            *reinterpret_cast<float4*>(As + r * STR + c4) = v;
        }
        __syncthreads();

        #pragma unroll 8
        for (int k = 0; k < KC; k++) {
            float4 w = *reinterpret_cast<const float4*>(Ws + k * 64 + cb);
            float a0 = As[(r0 + 0) * STR + k];
            float a1 = As[(r0 + 1) * STR + k];
            float a2 = As[(r0 + 2) * STR + k];
            float a3 = As[(r0 + 3) * STR + k];
            acc[0][0] = fmaf(a0, w.x, acc[0][0]);
            acc[0][1] = fmaf(a0, w.y, acc[0][1]);
            acc[0][2] = fmaf(a0, w.z, acc[0][2]);
            acc[0][3] = fmaf(a0, w.w, acc[0][3]);
            acc[1][0] = fmaf(a1, w.x, acc[1][0]);
            acc[1][1] = fmaf(a1, w.y, acc[1][1]);
            acc[1][2] = fmaf(a1, w.z, acc[1][2]);
            acc[1][3] = fmaf(a1, w.w, acc[1][3]);
            acc[2][0] = fmaf(a2, w.x, acc[2][0]);
            acc[2][1] = fmaf(a2, w.y, acc[2][1]);
            acc[2][2] = fmaf(a2, w.z, acc[2][2]);
            acc[2][3] = fmaf(a2, w.w, acc[2][3]);
            acc[3][0] = fmaf(a3, w.x, acc[3][0]);
            acc[3][1] = fmaf(a3, w.y, acc[3][1]);
            acc[3][2] = fmaf(a3, w.z, acc[3][2]);
            acc[3][3] = fmaf(a3, w.w, acc[3][3]);
        }
    }

    const float4 bv = *reinterpret_cast<const float4*>(bias + cb);

    #pragma unroll
    for (int j = 0; j < 4; j++) {
        int gr = row0 + r0 + j;
        if (gr >= N) break;
        float4 v;
        v.x = acc[j][0] + bv.x; v.y = acc[j][1] + bv.y;
        v.z = acc[j][2] + bv.z; v.w = acc[j][3] + bv.w;
        if (RELU) {
            v.x = fmaxf(v.x, 0.f); v.y = fmaxf(v.y, 0.f);
            v.z = fmaxf(v.z, 0.f); v.w = fmaxf(v.w, 0.f);
        }
        *reinterpret_cast<float4*>(out + (size_t)gr * 64 + cb) = v;
    }

    if (ZERO_AUX) {
        // Zero aux rows [row0, row0+64): 1024 float4s, coalesced
        float4 z = make_float4(0.f, 0.f, 0.f, 0.f);
        float4* a4 = reinterpret_cast<float4*>(aux) + (size_t)row0 * 16;
        int lim = (N - row0 < ROWS ? N - row0 : ROWS) * 16;
        for (int i = tid; i < lim; i += 256) a4[i] = z;
    }
}

// ---------------------------------------------------------------------------
// Vector reduction: red.global.add.v4.f32 (sm_90+)
// ---------------------------------------------------------------------------
__device__ __forceinline__ void red_add_v4(float* p, float4 v) {
    asm volatile("red.global.add.v4.f32 [%0], {%1, %2, %3, %4};"
                 :: "l"(p), "f"(v.x), "f"(v.y), "f"(v.z), "f"(v.w)
                 : "memory");
}

// ---------------------------------------------------------------------------
// Edge scatter: agg[dst] += h[src].  Half-warp per edge, float4 per lane.
// ---------------------------------------------------------------------------
__global__ void scatter_kernel(const float* __restrict__ h,
                               const int* __restrict__ ei,
                               float* __restrict__ agg) {
    int warp = blockIdx.x * 8 + (threadIdx.x >> 5);
    int lane = threadIdx.x & 31;
    int e = warp * 2 + (lane >> 4);
    if (e >= NE) return;
    int l16 = lane & 15;
    int s = __ldg(ei + e);
    int d = __ldg(ei + NE + e);
    if ((unsigned)s >= NN || (unsigned)d >= NN) return;
    float4 v = reinterpret_cast<const float4*>(h + (size_t)s * NH)[l16];
    red_add_v4(agg + (size_t)d * NH + l16 * 4, v);
}

// ---------------------------------------------------------------------------
// Global add pool: pool[batch[n]] += h[n].  Half-warp per node.
// ---------------------------------------------------------------------------
__global__ void pool_kernel(const float* __restrict__ h,
                            const int* __restrict__ batch,
                            float* __restrict__ pool) {
    int warp = blockIdx.x * 8 + (threadIdx.x >> 5);
    int lane = threadIdx.x & 31;
    int n = warp * 2 + (lane >> 4);
    if (n >= NN) return;
    int l16 = lane & 15;
    int g = __ldg(batch + n);
    if ((unsigned)g >= NG) return;
    float4 v = reinterpret_cast<const float4*>(h + (size_t)n * NH)[l16];
    red_add_v4(pool + (size_t)g * NH + l16 * 4, v);
}

// ---------------------------------------------------------------------------
// Readout: logits = g2 @ roW + rob; out = log_softmax(logits).
// ---------------------------------------------------------------------------
__global__ void readout_kernel(const float* __restrict__ g2,
                               const float* __restrict__ roW,
                               const float* __restrict__ rob,
                               float* __restrict__ out) {
    int row = blockIdx.x * 8 + (threadIdx.x >> 5);
    if (row >= NG) return;
    int lane = threadIdx.x & 31;

    float acc = 0.f;
    if (lane < NC) {
        acc = rob[lane];
        #pragma unroll
        for (int k = 0; k < NH; k++)
            acc = fmaf(g2[(size_t)row * NH + k], roW[k * NC + lane], acc);
    }
    float m = (lane < NC) ? acc : -3.4e38f;
    #pragma unroll
    for (int o = 16; o > 0; o >>= 1)
        m = fmaxf(m, __shfl_xor_sync(0xffffffffu, m, o));
    float e = (lane < NC) ? expf(acc - m) : 0.f;
    float s = e;
    #pragma unroll
    for (int o = 16; o > 0; o >>= 1)
        s += __shfl_xor_sync(0xffffffffu, s, o);
    if (lane < NC) out[(size_t)row * NC + lane] = acc - m - logf(s);
}

// ---------------------------------------------------------------------------
extern "C" void kernel_launch(void* const* d_in, const int* in_sizes, int n_in,
                              void* d_out, int out_size) {
    const float* x      = (const float*)d_in[0];
    const int*   ei     = (const int*)d_in[1];
    const int*   batch  = (const int*)d_in[2];
    const float* pre_w  = (const float*)d_in[3];
    const float* pre_b  = (const float*)d_in[4];
    const float* w1     = (const float*)d_in[5];
    const float* b1     = (const float*)d_in[6];
    const float* w2     = (const float*)d_in[7];
    const float* b2     = (const float*)d_in[8];
    const float* post_w = (const float*)d_in[9];
    const float* post_b = (const float*)d_in[10];
    const float* ro_w   = (const float*)d_in[11];
    const float* ro_b   = (const float*)d_in[12];
    float*       out    = (float*)d_out;

    float *hP, *aggP, *tP, *poolP, *g2P;
    cudaGetSymbolAddress((void**)&hP,    g_h);
    cudaGetSymbolAddress((void**)&aggP,  g_agg);
    cudaGetSymbolAddress((void**)&tP,    g_t);
    cudaGetSymbolAddress((void**)&poolP, g_pool);
    cudaGetSymbolAddress((void**)&g2P,   g_g2);

    const int GB = (NN + 63) / 64;

    // h = x @ pre_w + pre_b  ; also zero agg for layer 0
    gemm_kernel<NF, false, false, true><<<GB, 256>>>(
        x, nullptr, pre_w, pre_b, hP, aggP, NN);

    for (int l = 0; l < NL; l++) {
        scatter_kernel<<<(NE / 2 + 7) / 8, 256>>>(hP, ei, aggP);
        // t = relu((h + agg) @ w1 + b1)
        gemm_kernel<NH, true, true, false><<<GB, 256>>>(
            hP, aggP, w1 + l * NH * NH, b1 + l * NH, tP, nullptr, NN);
        // h = relu(t @ w2 + b2) ; also zero agg for next layer
        gemm_kernel<NH, true, false, true><<<GB, 256>>>(
            tP, nullptr, w2 + l * NH * NH, b2 + l * NH, hP, aggP, NN);
    }

    zero_kernel<<<64, 256>>>(poolP, NG * NH / 4);
    pool_kernel<<<(NN / 2 + 7) / 8, 256>>>(hP, batch, poolP);
    // g2 = relu(pool @ post_w + post_b)
    gemm_kernel<NH, true, false, false><<<(NG + 63) / 64, 256>>>(
        poolP, nullptr, post_w, post_b, g2P, nullptr, NG);
    readout_kernel<<<(NG + 7) / 8, 256>>>(g2P, ro_w, ro_b, out);
}

// round 8
// speedup vs baseline: 1.6232x; 1.1003x over previous
#include <cuda_runtime.h>
#include <cstdint>

#define NN 100000   // nodes
#define NE 1600000  // edges
#define NF 128      // input features
#define NH 64       // hidden
#define NC 10       // classes
#define NL 3        // layers
#define NG 1000     // graphs

// Scratch (device globals: no allocation allowed in kernel_launch)
__device__ float g_h[NN * NH];
__device__ float g_agg[NN * NH];
__device__ float g_pool[NG * NH];
__device__ float g_g2[NG * NH];

#define STR 68  // A-tile row stride in floats (272B: 16B-aligned, bank-padded)

// ---------------------------------------------------------------------------
// Core 64x64x64 register-tile GEMM step: acc += As(64xKC) @ Ws(KCx64)
// Per-thread 4 rows x 4 cols. A loads vectorized along k (LDS.128).
// ---------------------------------------------------------------------------
__device__ __forceinline__ void gemm_tile(const float* __restrict__ Ws,
                                          const float* __restrict__ As,
                                          int r0, int cb, float acc[4][4]) {
    #pragma unroll 4
    for (int k = 0; k < 64; k += 4) {
        float a0[4], a1[4], a2[4], a3[4];
        *reinterpret_cast<float4*>(a0) =
            *reinterpret_cast<const float4*>(As + (r0 + 0) * STR + k);
        *reinterpret_cast<float4*>(a1) =
            *reinterpret_cast<const float4*>(As + (r0 + 1) * STR + k);
        *reinterpret_cast<float4*>(a2) =
            *reinterpret_cast<const float4*>(As + (r0 + 2) * STR + k);
        *reinterpret_cast<float4*>(a3) =
            *reinterpret_cast<const float4*>(As + (r0 + 3) * STR + k);
        #pragma unroll
        for (int kk = 0; kk < 4; kk++) {
            float4 w = *reinterpret_cast<const float4*>(Ws + (k + kk) * 64 + cb);
            acc[0][0] = fmaf(a0[kk], w.x, acc[0][0]);
            acc[0][1] = fmaf(a0[kk], w.y, acc[0][1]);
            acc[0][2] = fmaf(a0[kk], w.z, acc[0][2]);
            acc[0][3] = fmaf(a0[kk], w.w, acc[0][3]);
            acc[1][0] = fmaf(a1[kk], w.x, acc[1][0]);
            acc[1][1] = fmaf(a1[kk], w.y, acc[1][1]);
            acc[1][2] = fmaf(a1[kk], w.z, acc[1][2]);
            acc[1][3] = fmaf(a1[kk], w.w, acc[1][3]);
            acc[2][0] = fmaf(a2[kk], w.x, acc[2][0]);
            acc[2][1] = fmaf(a2[kk], w.y, acc[2][1]);
            acc[2][2] = fmaf(a2[kk], w.z, acc[2][2]);
            acc[2][3] = fmaf(a2[kk], w.w, acc[2][3]);
            acc[3][0] = fmaf(a3[kk], w.x, acc[3][0]);
            acc[3][1] = fmaf(a3[kk], w.y, acc[3][1]);
            acc[3][2] = fmaf(a3[kk], w.z, acc[3][2]);
            acc[3][3] = fmaf(a3[kk], w.w, acc[3][3]);
        }
    }
}

// ---------------------------------------------------------------------------
// Generic GEMM: out[N,64] = act( (A [+A2]) [N,K] @ W[K,64] + b ), K in {64,128}
// ZERO_AUX: epilogue zeroes aux rows [row0, row0+64).
// ---------------------------------------------------------------------------
template <int K, bool RELU, bool ADD2, bool ZERO_AUX>
__global__ __launch_bounds__(256)
void gemm_kernel(const float* __restrict__ A,
                 const float* __restrict__ A2,
                 const float* __restrict__ W,
                 const float* __restrict__ bias,
                 float* __restrict__ out,
                 float* __restrict__ aux, int N) {
    constexpr int ROWS = 64;
    constexpr int KC   = 64;
    constexpr int NCHK = K / KC;

    __shared__ float Ws[KC * 64];
    __shared__ float As[ROWS * STR];

    const int tid  = threadIdx.x;
    const int row0 = blockIdx.x * ROWS;
    const int cb = (tid & 15) * 4;
    const int r0 = (tid >> 4) * 4;

    float acc[4][4];
    #pragma unroll
    for (int j = 0; j < 4; j++)
        #pragma unroll
        for (int c = 0; c < 4; c++) acc[j][c] = 0.f;

    #pragma unroll
    for (int kc = 0; kc < NCHK; kc++) {
        if (kc > 0) __syncthreads();
        {
            const float4* W4 = reinterpret_cast<const float4*>(W) + kc * 1024;
            float4* Ws4 = reinterpret_cast<float4*>(Ws);
            #pragma unroll
            for (int i = 0; i < 4; i++) Ws4[tid + i * 256] = W4[tid + i * 256];
        }
        #pragma unroll
        for (int i = 0; i < 4; i++) {
            int idx = tid + i * 256;
            int r  = idx >> 4;
            int c4 = (idx & 15) * 4;
            int gr = row0 + r;
            float4 v = make_float4(0.f, 0.f, 0.f, 0.f);
            if (gr < N) {
                size_t gi = (size_t)gr * K + kc * KC + c4;
                v = *reinterpret_cast<const float4*>(A + gi);
                if (ADD2) {
                    float4 w = *reinterpret_cast<const float4*>(A2 + gi);
                    v.x += w.x; v.y += w.y; v.z += w.z; v.w += w.w;
                }
            }
            *reinterpret_cast<float4*>(As + r * STR + c4) = v;
        }
        __syncthreads();
        gemm_tile(Ws, As, r0, cb, acc);
    }

    const float4 bv = *reinterpret_cast<const float4*>(bias + cb);
    #pragma unroll
    for (int j = 0; j < 4; j++) {
        int gr = row0 + r0 + j;
        if (gr >= N) break;
        float4 v;
        v.x = acc[j][0] + bv.x; v.y = acc[j][1] + bv.y;
        v.z = acc[j][2] + bv.z; v.w = acc[j][3] + bv.w;
        if (RELU) {
            v.x = fmaxf(v.x, 0.f); v.y = fmaxf(v.y, 0.f);
            v.z = fmaxf(v.z, 0.f); v.w = fmaxf(v.w, 0.f);
        }
        *reinterpret_cast<float4*>(out + (size_t)gr * 64 + cb) = v;
    }

    if (ZERO_AUX) {
        float4 z = make_float4(0.f, 0.f, 0.f, 0.f);
        float4* a4 = reinterpret_cast<float4*>(aux) + (size_t)row0 * 16;
        int lim = (N - row0 < ROWS ? N - row0 : ROWS) * 16;
        for (int i = tid; i < lim; i += 256) a4[i] = z;
    }
}

// ---------------------------------------------------------------------------
// Fused GIN conv MLP: h = relu( relu((h+agg)@W1+b1) @ W2 + b2 ), in place.
// t tile kept in smem (As reused); W2 overwrites W1 in Ws. Zeroes agg.
// ---------------------------------------------------------------------------
__global__ __launch_bounds__(256)
void conv_kernel(float* __restrict__ h,
                 const float* __restrict__ agg,
                 const float* __restrict__ W1,
                 const float* __restrict__ b1,
                 const float* __restrict__ W2,
                 const float* __restrict__ b2,
                 float* __restrict__ aggz, int N) {
    constexpr int ROWS = 64;

    __shared__ float Ws[64 * 64];
    __shared__ float As[ROWS * STR];

    const int tid  = threadIdx.x;
    const int row0 = blockIdx.x * ROWS;
    const int cb = (tid & 15) * 4;
    const int r0 = (tid >> 4) * 4;

    // Stage W1 + A (= h + agg)
    {
        const float4* W4 = reinterpret_cast<const float4*>(W1);
        float4* Ws4 = reinterpret_cast<float4*>(Ws);
        #pragma unroll
        for (int i = 0; i < 4; i++) Ws4[tid + i * 256] = W4[tid + i * 256];
    }
    #pragma unroll
    for (int i = 0; i < 4; i++) {
        int idx = tid + i * 256;
        int r  = idx >> 4;
        int c4 = (idx & 15) * 4;
        int gr = row0 + r;
        float4 v = make_float4(0.f, 0.f, 0.f, 0.f);
        if (gr < N) {
            size_t gi = (size_t)gr * 64 + c4;
            v = *reinterpret_cast<const float4*>(h + gi);
            float4 w = *reinterpret_cast<const float4*>(agg + gi);
            v.x += w.x; v.y += w.y; v.z += w.z; v.w += w.w;
        }
        *reinterpret_cast<float4*>(As + r * STR + c4) = v;
    }
    __syncthreads();

    // GEMM1
    float acc[4][4];
    #pragma unroll
    for (int j = 0; j < 4; j++)
        #pragma unroll
        for (int c = 0; c < 4; c++) acc[j][c] = 0.f;
    gemm_tile(Ws, As, r0, cb, acc);
    __syncthreads();  // done reading As/Ws

    // t = relu(acc + b1) -> As ; stage W2 -> Ws
    {
        const float4 bv = *reinterpret_cast<const float4*>(b1 + cb);
        #pragma unroll
        for (int j = 0; j < 4; j++) {
            float4 v;
            v.x = fmaxf(acc[j][0] + bv.x, 0.f);
            v.y = fmaxf(acc[j][1] + bv.y, 0.f);
            v.z = fmaxf(acc[j][2] + bv.z, 0.f);
            v.w = fmaxf(acc[j][3] + bv.w, 0.f);
            *reinterpret_cast<float4*>(As + (r0 + j) * STR + cb) = v;
        }
        const float4* W4 = reinterpret_cast<const float4*>(W2);
        float4* Ws4 = reinterpret_cast<float4*>(Ws);
        #pragma unroll
        for (int i = 0; i < 4; i++) Ws4[tid + i * 256] = W4[tid + i * 256];
    }
    __syncthreads();

    // GEMM2
    #pragma unroll
    for (int j = 0; j < 4; j++)
        #pragma unroll
        for (int c = 0; c < 4; c++) acc[j][c] = 0.f;
    gemm_tile(Ws, As, r0, cb, acc);

    // h = relu(acc + b2), in place
    const float4 bv = *reinterpret_cast<const float4*>(b2 + cb);
    #pragma unroll
    for (int j = 0; j < 4; j++) {
        int gr = row0 + r0 + j;
        if (gr >= N) break;
        float4 v;
        v.x = fmaxf(acc[j][0] + bv.x, 0.f);
        v.y = fmaxf(acc[j][1] + bv.y, 0.f);
        v.z = fmaxf(acc[j][2] + bv.z, 0.f);
        v.w = fmaxf(acc[j][3] + bv.w, 0.f);
        *reinterpret_cast<float4*>(h + (size_t)gr * 64 + cb) = v;
    }

    // Zero agg rows for next layer
    {
        float4 z = make_float4(0.f, 0.f, 0.f, 0.f);
        float4* a4 = reinterpret_cast<float4*>(aggz) + (size_t)row0 * 16;
        int lim = (N - row0 < ROWS ? N - row0 : ROWS) * 16;
        for (int i = tid; i < lim; i += 256) a4[i] = z;
    }
}

// ---------------------------------------------------------------------------
__global__ void zero_kernel(float* __restrict__ p, int n4) {
    float4 z = make_float4(0.f, 0.f, 0.f, 0.f);
    for (int i = blockIdx.x * blockDim.x + threadIdx.x; i < n4;
         i += gridDim.x * blockDim.x)
        reinterpret_cast<float4*>(p)[i] = z;
}

__device__ __forceinline__ void red_add_v4(float* p, float4 v) {
    asm volatile("red.global.add.v4.f32 [%0], {%1, %2, %3, %4};"
                 :: "l"(p), "f"(v.x), "f"(v.y), "f"(v.z), "f"(v.w)
                 : "memory");
}

__global__ void scatter_kernel(const float* __restrict__ h,
                               const int* __restrict__ ei,
                               float* __restrict__ agg) {
    int warp = blockIdx.x * 8 + (threadIdx.x >> 5);
    int lane = threadIdx.x & 31;
    int e = warp * 2 + (lane >> 4);
    if (e >= NE) return;
    int l16 = lane & 15;
    int s = __ldg(ei + e);
    int d = __ldg(ei + NE + e);
    if ((unsigned)s >= NN || (unsigned)d >= NN) return;
    float4 v = reinterpret_cast<const float4*>(h + (size_t)s * NH)[l16];
    red_add_v4(agg + (size_t)d * NH + l16 * 4, v);
}

__global__ void pool_kernel(const float* __restrict__ h,
                            const int* __restrict__ batch,
                            float* __restrict__ pool) {
    int warp = blockIdx.x * 8 + (threadIdx.x >> 5);
    int lane = threadIdx.x & 31;
    int n = warp * 2 + (lane >> 4);
    if (n >= NN) return;
    int l16 = lane & 15;
    int g = __ldg(batch + n);
    if ((unsigned)g >= NG) return;
    float4 v = reinterpret_cast<const float4*>(h + (size_t)n * NH)[l16];
    red_add_v4(pool + (size_t)g * NH + l16 * 4, v);
}

__global__ void readout_kernel(const float* __restrict__ g2,
                               const float* __restrict__ roW,
                               const float* __restrict__ rob,
                               float* __restrict__ out) {
    int row = blockIdx.x * 8 + (threadIdx.x >> 5);
    if (row >= NG) return;
    int lane = threadIdx.x & 31;

    float acc = 0.f;
    if (lane < NC) {
        acc = rob[lane];
        #pragma unroll
        for (int k = 0; k < NH; k++)
            acc = fmaf(g2[(size_t)row * NH + k], roW[k * NC + lane], acc);
    }
    float m = (lane < NC) ? acc : -3.4e38f;
    #pragma unroll
    for (int o = 16; o > 0; o >>= 1)
        m = fmaxf(m, __shfl_xor_sync(0xffffffffu, m, o));
    float e = (lane < NC) ? expf(acc - m) : 0.f;
    float s = e;
    #pragma unroll
    for (int o = 16; o > 0; o >>= 1)
        s += __shfl_xor_sync(0xffffffffu, s, o);
    if (lane < NC) out[(size_t)row * NC + lane] = acc - m - logf(s);
}

// ---------------------------------------------------------------------------
extern "C" void kernel_launch(void* const* d_in, const int* in_sizes, int n_in,
                              void* d_out, int out_size) {
    const float* x      = (const float*)d_in[0];
    const int*   ei     = (const int*)d_in[1];
    const int*   batch  = (const int*)d_in[2];
    const float* pre_w  = (const float*)d_in[3];
    const float* pre_b  = (const float*)d_in[4];
    const float* w1     = (const float*)d_in[5];
    const float* b1     = (const float*)d_in[6];
    const float* w2     = (const float*)d_in[7];
    const float* b2     = (const float*)d_in[8];
    const float* post_w = (const float*)d_in[9];
    const float* post_b = (const float*)d_in[10];
    const float* ro_w   = (const float*)d_in[11];
    const float* ro_b   = (const float*)d_in[12];
    float*       out    = (float*)d_out;

    float *hP, *aggP, *poolP, *g2P;
    cudaGetSymbolAddress((void**)&hP,    g_h);
    cudaGetSymbolAddress((void**)&aggP,  g_agg);
    cudaGetSymbolAddress((void**)&poolP, g_pool);
    cudaGetSymbolAddress((void**)&g2P,   g_g2);

    const int GB = (NN + 63) / 64;

    // h = x @ pre_w + pre_b ; zero agg for layer 0
    gemm_kernel<NF, false, false, true><<<GB, 256>>>(
        x, nullptr, pre_w, pre_b, hP, aggP, NN);

    for (int l = 0; l < NL; l++) {
        scatter_kernel<<<(NE / 2 + 7) / 8, 256>>>(hP, ei, aggP);
        // h = relu(relu((h+agg)@w1+b1)@w2+b2), in place; zero agg
        conv_kernel<<<GB, 256>>>(hP, aggP,
                                 w1 + l * NH * NH, b1 + l * NH,
                                 w2 + l * NH * NH, b2 + l * NH,
                                 aggP, NN);
    }

    zero_kernel<<<64, 256>>>(poolP, NG * NH / 4);
    pool_kernel<<<(NN / 2 + 7) / 8, 256>>>(hP, batch, poolP);
    // g2 = relu(pool @ post_w + post_b)
    gemm_kernel<NH, true, false, false><<<(NG + 63) / 64, 256>>>(
        poolP, nullptr, post_w, post_b, g2P, nullptr, NG);
    readout_kernel<<<(NG + 7) / 8, 256>>>(g2P, ro_w, ro_b, out);
}